// round 14
// baseline (speedup 1.0000x reference)
#include <cuda_runtime.h>
#include <cuda_bf16.h>
#include <cstdint>

#define H 64
#define V 128
#define S 64
#define BATCH 256
#define L 4096

typedef unsigned long long u64;
typedef unsigned int u32;
typedef unsigned short u16;

// Scratch (no allocs allowed)
__device__ float d_hn[V * H];      // LN'd hidden per vocab id
__device__ float d_gTf[S * V];     // gate softmax, transposed [s][v], fp32
__device__ u64   d_Bfrag[64 * 64]; // [p=vpair][h]: lo32 = bf16x2 hi-parts, hi32 = lo

__device__ __forceinline__ u32 pack_bf16x2(float lo, float hi) {
    u32 d;
    asm("cvt.rn.bf16x2.f32 %0, %1, %2;" : "=r"(d) : "f"(hi), "f"(lo));
    return d;
}
__device__ __forceinline__ float bflo(u32 p) { return __uint_as_float(p << 16); }
__device__ __forceinline__ float bfhi(u32 p) { return __uint_as_float(p & 0xFFFF0000u); }

__device__ __forceinline__ void mma_bf16(float* c, u32 a0, u32 a1, u32 a2, u32 a3,
                                         u32 b0, u32 b1) {
    asm volatile(
        "mma.sync.aligned.m16n8k16.row.col.f32.bf16.bf16.f32 "
        "{%0,%1,%2,%3}, {%4,%5,%6,%7}, {%8,%9}, {%0,%1,%2,%3};"
        : "+f"(c[0]), "+f"(c[1]), "+f"(c[2]), "+f"(c[3])
        : "r"(a0), "r"(a1), "r"(a2), "r"(a3), "r"(b0), "r"(b1));
}

// ---------------------------------------------------------------------------
// Kernel 1: per-vocab precompute ONLY (R13-proven). grid = 128, 128 threads.
// ---------------------------------------------------------------------------
__global__ void __launch_bounds__(128) prep_kernel(
        const float* __restrict__ embed_w,
        const float* __restrict__ w1,
        const float* __restrict__ b1,
        const float* __restrict__ w2,
        const float* __restrict__ b2,
        const float* __restrict__ ln_g,
        const float* __restrict__ ln_b,
        const float* __restrict__ gate_w,
        const float* __restrict__ gate_b) {
    int t = threadIdx.x;
    int lane = t & 31;
    int warp = t >> 5;
    int v = blockIdx.x;

    __shared__ float hs[H];
    __shared__ float us[2 * H];
    __shared__ float hns[H];
    __shared__ float wred[2][2];

    if (t < H) hs[t] = embed_w[v * H + t];
    __syncthreads();

    {
        float a0 = b1[t], a1 = 0.0f;
#pragma unroll
        for (int k = 0; k < H; k += 2) {
            a0 = fmaf(hs[k],     w1[k * (2 * H) + t],       a0);
            a1 = fmaf(hs[k + 1], w1[(k + 1) * (2 * H) + t], a1);
        }
        us[t] = fmaxf(a0 + a1, 0.0f);
    }
    __syncthreads();

    float xval = 0.0f;
    if (t < H) {
        float a0 = b2[t], a1 = 0.0f;
#pragma unroll
        for (int k = 0; k < 2 * H; k += 2) {
            a0 = fmaf(us[k],     w2[k * H + t],       a0);
            a1 = fmaf(us[k + 1], w2[(k + 1) * H + t], a1);
        }
        xval = hs[t] + a0 + a1;
        float s = xval, sq = xval * xval;
#pragma unroll
        for (int off = 16; off > 0; off >>= 1) {
            s  += __shfl_xor_sync(0xffffffffu, s, off);
            sq += __shfl_xor_sync(0xffffffffu, sq, off);
        }
        if (lane == 0) { wred[warp][0] = s; wred[warp][1] = sq; }
    }
    __syncthreads();

    if (t < H) {
        float s  = wred[0][0] + wred[1][0];
        float sq = wred[0][1] + wred[1][1];
        float mu = s * (1.0f / H);
        float var = sq * (1.0f / H) - mu * mu;
        float rstd = rsqrtf(var + 1e-5f);
        float val = (xval - mu) * rstd * ln_g[t] + ln_b[t];
        hns[t] = val;
        d_hn[v * H + t] = val;
    }
    __syncthreads();

    float l = 0.0f;
    if (t < S) {
        float a0 = gate_b[t], a1 = 0.0f;
#pragma unroll
        for (int k = 0; k < H; k += 2) {
            a0 = fmaf(hns[k],     gate_w[k * S + t],       a0);
            a1 = fmaf(hns[k + 1], gate_w[(k + 1) * S + t], a1);
        }
        l = a0 + a1;
        float m = l;
#pragma unroll
        for (int off = 16; off > 0; off >>= 1)
            m = fmaxf(m, __shfl_xor_sync(0xffffffffu, m, off));
        if (lane == 0) wred[warp][0] = m;
    }
    __syncthreads();

    float ev = 0.0f;
    if (t < S) {
        float m = fmaxf(wred[0][0], wred[1][0]);
        ev = expf(l - m);
        float ssum = ev;
#pragma unroll
        for (int off = 16; off > 0; off >>= 1)
            ssum += __shfl_xor_sync(0xffffffffu, ssum, off);
        if (lane == 0) wred[warp][1] = ssum;
    }
    __syncthreads();

    if (t < S) {
        d_gTf[t * V + v] = ev / (wred[0][1] + wred[1][1]);
    } else {
        int h = t - 64;
        float x = hns[h];
        __nv_bfloat16 hb = __float2bfloat16(x);
        float hf = __bfloat162float(hb);
        __nv_bfloat16 lb = __float2bfloat16(x - hf);
        int p = v >> 1, par = v & 1;
        u16* q = (u16*)d_Bfrag;
        q[(p * 64 + h) * 4 + par]     = *(u16*)&hb;
        q[(p * 64 + h) * 4 + 2 + par] = *(u16*)&lb;
    }
}

// ---------------------------------------------------------------------------
// Kernel 2: one batch per block, 256 threads = 8 warps.
// hist -> smem A-frag build -> pure-LDS MMA -> compressed epilogue.
// ---------------------------------------------------------------------------
#define FPAD 68   // u64-unit stride for Af/Bf (conflict-free: 68 mod 16 == 4)

struct FinalSmem {
    int sub[8][V];          // 4096 B
    u64 Bf[64 * FPAD];      // 34816 B
    u64 Af[64 * FPAD];      // 34816 B  [s][p] gate*cnt hi/lo fragments
    float skeys[S][FPAD];   // 17408 B
    float cs[V];
    float sq[H];
    float ssim[S];
    float sattn[S];
    float sctx[H];
    float sout[V];
};

__global__ void __launch_bounds__(256, 2) final_kernel(
        const int* __restrict__ seq,
        const float* __restrict__ slot_keys,
        const float* __restrict__ out_w,
        const float* __restrict__ out_b,
        float* __restrict__ out) {
    extern __shared__ char smraw[];
    FinalSmem& sm = *(FinalSmem*)smraw;

    int b = blockIdx.x;
    int t = threadIdx.x;
    int lane = t & 31;
    int warp = t >> 5;
    int gid = lane >> 2;
    int tig = lane & 3;

    const int wm = warp & 3;
    const int wn = warp >> 2;
    const int row0 = wm * 16 + gid;

    int qi = seq[b * L + (L - 1)];

    for (int i = t; i < 8 * V; i += 256) ((int*)sm.sub)[i] = 0;
    __syncthreads();  // B0

    // Bf copy + sq + slot_keys prefetch + hist (independent streams of work)
#pragma unroll
    for (int i = t; i < 2048; i += 256) {
        int idx = 2 * i;
        int p = idx >> 6, h = idx & 63;
        ulonglong2 w2v = *(const ulonglong2*)&d_Bfrag[p * 64 + h];
        *(ulonglong2*)&sm.Bf[p * FPAD + h] = w2v;
    }
    if (t < H) sm.sq[t] = d_hn[qi * H + t];

    float2 sk0[4], sk1[4];
#pragma unroll
    for (int nt = 0; nt < 4; nt++) {
        int col = (wn * 4 + nt) * 8 + tig * 2;
        sk0[nt] = *(const float2*)&slot_keys[row0 * H + col];
        sk1[nt] = *(const float2*)&slot_keys[(row0 + 8) * H + col];
    }

    {
        const int4* s4 = (const int4*)(seq + b * L);
        for (int i = t; i < 1023; i += 256) {
            int4 x = s4[i];
            atomicAdd(&sm.sub[warp][x.x], 1);
            atomicAdd(&sm.sub[warp][x.y], 1);
            atomicAdd(&sm.sub[warp][x.z], 1);
            atomicAdd(&sm.sub[warp][x.w], 1);
        }
        if (t < 3) atomicAdd(&sm.sub[warp][seq[b * L + 4092 + t]], 1);
    }
    __syncthreads();  // B1

    if (t < V) {
        int tot = 0;
#pragma unroll
        for (int k = 0; k < 8; k++) tot += sm.sub[k][t];
        sm.cs[t] = (float)tot;
    }
    __syncthreads();  // B2

    // ---- Af build: [s][p] = {hi,lo} of (gTf[s][2p..2p+1] * cs[2p..2p+1]) ----
    {
        int s = t & 63;
        int pbase = (t >> 6) * 16;
        const float* grow = d_gTf + s * V;
#pragma unroll
        for (int jj = 0; jj < 8; jj++) {
            int p = pbase + 2 * jj;
            float4 g = *(const float4*)&grow[2 * p];
            float4 c = *(const float4*)&sm.cs[2 * p];
            float x0 = g.x * c.x, x1 = g.y * c.y, x2 = g.z * c.z, x3 = g.w * c.w;
            u32 hi0 = pack_bf16x2(x0, x1);
            u32 lo0 = pack_bf16x2(x0 - bflo(hi0), x1 - bfhi(hi0));
            u32 hi1 = pack_bf16x2(x2, x3);
            u32 lo1 = pack_bf16x2(x2 - bflo(hi1), x3 - bfhi(hi1));
            sm.Af[s * FPAD + p]     = (u64)hi0 | ((u64)lo0 << 32);
            sm.Af[s * FPAD + p + 1] = (u64)hi1 | ((u64)lo1 << 32);
        }
    }
    __syncthreads();  // B3

    // ---- MMA: pure LDS ----
    float acc[4][4];
#pragma unroll
    for (int nt = 0; nt < 4; nt++)
#pragma unroll
        for (int i = 0; i < 4; i++) acc[nt][i] = 0.0f;

#pragma unroll
    for (int kt = 0; kt < 8; kt++) {
        int pb = kt * 8 + tig;
        u64 A0 = sm.Af[row0 * FPAD + pb];
        u64 A1 = sm.Af[(row0 + 8) * FPAD + pb];
        u64 A2 = sm.Af[row0 * FPAD + pb + 4];
        u64 A3 = sm.Af[(row0 + 8) * FPAD + pb + 4];
        u32 aH0 = (u32)A0, aL0 = (u32)(A0 >> 32);
        u32 aH1 = (u32)A1, aL1 = (u32)(A1 >> 32);
        u32 aH2 = (u32)A2, aL2 = (u32)(A2 >> 32);
        u32 aH3 = (u32)A3, aL3 = (u32)(A3 >> 32);
#pragma unroll
        for (int nt = 0; nt < 4; nt++) {
            int h = (wn * 4 + nt) * 8 + gid;
            u64 B0 = sm.Bf[pb * FPAD + h];
            u64 B1 = sm.Bf[(pb + 4) * FPAD + h];
            u32 bH0 = (u32)B0, bL0 = (u32)(B0 >> 32);
            u32 bH1 = (u32)B1, bL1 = (u32)(B1 >> 32);
            mma_bf16(acc[nt], aH0, aH1, aH2, aH3, bH0, bH1);
            mma_bf16(acc[nt], aH0, aH1, aH2, aH3, bL0, bL1);
            mma_bf16(acc[nt], aL0, aL1, aL2, aL3, bH0, bH1);
        }
    }

    // keys (+ prefetched slot_keys) -> shared
#pragma unroll
    for (int nt = 0; nt < 4; nt++) {
        int col = (wn * 4 + nt) * 8 + tig * 2;
        sm.skeys[row0][col]         = acc[nt][0] + sk0[nt].x;
        sm.skeys[row0][col + 1]     = acc[nt][1] + sk0[nt].y;
        sm.skeys[row0 + 8][col]     = acc[nt][2] + sk1[nt].x;
        sm.skeys[row0 + 8][col + 1] = acc[nt][3] + sk1[nt].y;
    }
    __syncthreads();  // B4

    // ---- sim: all 8 warps, slot = warp*8+gid, 4-lane h-split; in-warp qnorm ----
    {
        float q0 = sm.sq[lane], q1 = sm.sq[lane + 32];
        float qn = q0 * q0 + q1 * q1;
#pragma unroll
        for (int off = 16; off > 0; off >>= 1)
            qn += __shfl_xor_sync(0xffffffffu, qn, off);
        float qinv = rsqrtf(fmaxf(qn, 1e-24f));

        int slot = warp * 8 + gid;
        const float* row = sm.skeys[slot];
        int base = tig * 16;
        float dot = 0.0f, nk = 0.0f;
#pragma unroll
        for (int i = 0; i < 4; i++) {
            float4 kv = *(const float4*)&row[base + 4 * i];
            float4 qv = *(const float4*)&sm.sq[base + 4 * i];
            dot = fmaf(kv.x, qv.x, dot); nk = fmaf(kv.x, kv.x, nk);
            dot = fmaf(kv.y, qv.y, dot); nk = fmaf(kv.y, kv.y, nk);
            dot = fmaf(kv.z, qv.z, dot); nk = fmaf(kv.z, kv.z, nk);
            dot = fmaf(kv.w, qv.w, dot); nk = fmaf(kv.w, kv.w, nk);
        }
        dot += __shfl_xor_sync(0xffffffffu, dot, 1);
        dot += __shfl_xor_sync(0xffffffffu, dot, 2);
        nk  += __shfl_xor_sync(0xffffffffu, nk, 1);
        nk  += __shfl_xor_sync(0xffffffffu, nk, 2);
        if (tig == 0)
            sm.ssim[slot] = dot * qinv / fmaxf(sqrtf(nk), 1e-12f);
    }
    __syncthreads();  // B5

    // ---- softmax over 64, entirely in warp 0 (2 slots/lane) ----
    if (warp == 0) {
        float v0 = sm.ssim[lane], v1 = sm.ssim[lane + 32];
        float m = fmaxf(v0, v1);
#pragma unroll
        for (int off = 16; off > 0; off >>= 1)
            m = fmaxf(m, __shfl_xor_sync(0xffffffffu, m, off));
        float e0 = expf(v0 - m), e1 = expf(v1 - m);
        float s = e0 + e1;
#pragma unroll
        for (int off = 16; off > 0; off >>= 1)
            s += __shfl_xor_sync(0xffffffffu, s, off);
        float rs = 1.0f / s;
        sm.sattn[lane]      = e0 * rs;
        sm.sattn[lane + 32] = e1 * rs;
    }
    __syncthreads();  // B6

    // ---- ctx: h = t>>2, 4-lane n-split ----
    {
        int h = t >> 2, sub = t & 3;
        float c = 0.0f;
#pragma unroll
        for (int i = 0; i < 16; i++) {
            int n = sub * 16 + i;
            c = fmaf(sm.sattn[n], sm.skeys[n][h], c);
        }
        c += __shfl_xor_sync(0xffffffffu, c, 1);
        c += __shfl_xor_sync(0xffffffffu, c, 2);
        if (sub == 0) sm.sctx[h] = c;
    }
    __syncthreads();  // B7

    // ---- out GEMV: j = t&127, 2-way k-split via smem combine ----
    {
        int j = t & 127;
        int kh = (t >> 7) * 32;
        float o = 0.0f;
#pragma unroll
        for (int i = 0; i < 32; i++)
            o = fmaf(sm.sctx[kh + i], out_w[(kh + i) * V + j], o);
        if (t >= 128) sm.sout[j] = o;
        __syncthreads();  // B8
        if (t < 128) out[b * V + j] = o + sm.sout[j] + out_b[j];
    }
}

// ---------------------------------------------------------------------------
extern "C" void kernel_launch(void* const* d_in, const int* in_sizes, int n_in,
                              void* d_out, int out_size) {
    const int*   seq       = (const int*)d_in[0];
    const float* embed_w   = (const float*)d_in[1];
    const float* w1        = (const float*)d_in[2];
    const float* b1        = (const float*)d_in[3];
    const float* w2        = (const float*)d_in[4];
    const float* b2        = (const float*)d_in[5];
    const float* ln_g      = (const float*)d_in[6];
    const float* ln_b      = (const float*)d_in[7];
    const float* slot_keys = (const float*)d_in[8];
    // d_in[9] = slot_vals (unused: reference sets vals = keys)
    const float* gate_w    = (const float*)d_in[10];
    const float* gate_b    = (const float*)d_in[11];
    const float* out_w     = (const float*)d_in[12];
    const float* out_b     = (const float*)d_in[13];
    float* out = (float*)d_out;

    int smem_bytes = (int)sizeof(FinalSmem);
    cudaFuncSetAttribute(final_kernel,
                         cudaFuncAttributeMaxDynamicSharedMemorySize, smem_bytes);

    prep_kernel<<<V, 128>>>(embed_w, w1, b1, w2, b2, ln_g, ln_b, gate_w, gate_b);
    final_kernel<<<BATCH, 256, smem_bytes>>>(seq, slot_keys, out_w, out_b, out);
}